// round 4
// baseline (speedup 1.0000x reference)
#include <cuda_runtime.h>

// ---------------- problem constants ----------------
#define UN   100000
#define INUM 50000
#define DDIM 64
#define HH   4
#define DHH  16
#define HNN  128
#define NNZE 1000000

// ---------------- routed sparse pointers ----------------
__device__ const int*   g_rows[3];
__device__ const int*   g_cols[3];
__device__ const float* g_vals[3];

// ---------------- scratch (device globals; no allocation allowed) ----------------
__device__ float g_bufTU1[UN*DDIM];
__device__ float g_bufTU2[UN*DDIM];
__device__ float g_bufTI1[INUM*DDIM];
__device__ float g_bufTI2[INUM*DDIM];
__device__ float g_bufUU1[UN*DDIM];
__device__ float g_bufUU2[UN*DDIM];
__device__ float g_curbuf[UN*DDIM];
__device__ float g_t2buf[DDIM*HNN];
__device__ float g_t3buf[DDIM*HNN];
__device__ float g_scrbuf[2048];   // [0..1023]=VK, [1024..2047]=pre

// ---------------- router: detect metadata ordering of the 9 sparse arrays ----------------
// dict order:      8=adj_rows 9=adj_cols 10=adj_vals 11=tp_rows 12=tp_cols 13=tp_vals 14=uu_rows 15=uu_cols 16=uu_vals
// signature order: 8=adj_vals 9=tp_vals 10=uu_vals 11=adj_rows 12=adj_cols 13=tp_rows 14=tp_cols 15=uu_rows 16=uu_cols
// Row indices are < 100000 (0x186A0); float uniforms in [0,1) have bit patterns ~>= 0x3E000000.
__global__ void route_kernel(const void* a8, const void* a9, const void* a10,
                             const void* a11, const void* a12, const void* a13,
                             const void* a14, const void* a15, const void* a16)
{
    const unsigned* p = (const unsigned*)a8;
    unsigned m = 0;
    for (int i = 0; i < 32; ++i) { unsigned v = p[i]; m = (v > m) ? v : m; }
    if (m > 0x01000000u) {
        // signature order
        g_vals[0] = (const float*)a8;  g_vals[1] = (const float*)a9;  g_vals[2] = (const float*)a10;
        g_rows[0] = (const int*)a11;   g_cols[0] = (const int*)a12;
        g_rows[1] = (const int*)a13;   g_cols[1] = (const int*)a14;
        g_rows[2] = (const int*)a15;   g_cols[2] = (const int*)a16;
    } else {
        // dict order
        g_rows[0] = (const int*)a8;   g_cols[0] = (const int*)a9;   g_vals[0] = (const float*)a10;
        g_rows[1] = (const int*)a11;  g_cols[1] = (const int*)a12;  g_vals[1] = (const float*)a13;
        g_rows[2] = (const int*)a14;  g_cols[2] = (const int*)a15;  g_vals[2] = (const float*)a16;
    }
}

// ---------------- SpMM: out[r,:] += v * X[c,:]  (16 lanes per nnz, float4 + vector RED) ----------------
__global__ void spmm_kernel(int which, const float* __restrict__ X, float* __restrict__ out)
{
    int t = blockIdx.x * blockDim.x + threadIdx.x;
    int e = t >> 4;
    if (e >= NNZE) return;
    int lane = t & 15;
    const int*   rows = g_rows[which];
    const int*   cols = g_cols[which];
    const float* vals = g_vals[which];
    int   r = __ldg(&rows[e]);
    int   c = __ldg(&cols[e]);
    float v = __ldg(&vals[e]);
    float4 x = __ldg(((const float4*)X) + (size_t)c * 16 + lane);
    float4 y; y.x = v * x.x; y.y = v * x.y; y.z = v * x.z; y.w = v * x.w;
    float* p = out + (size_t)r * 64 + lane * 4;
    asm volatile("red.global.add.v4.f32 [%0], {%1, %2, %3, %4};"
                 :: "l"(p), "f"(y.x), "f"(y.y), "f"(y.z), "f"(y.w) : "memory");
}

// ---------------- fused: E0 = A + B1 + B2 ; Key[h,n,j] = sum_k E0[n,k]*K[k,h*16+j] ----------------
__global__ void embed_key_kernel(const float* __restrict__ A, const float* __restrict__ B1,
                                 const float* __restrict__ B2, const float* __restrict__ Kmat,
                                 float* __restrict__ E0, float* __restrict__ Key, int N)
{
    __shared__ float sK[4096];        // K[k*64+c]
    __shared__ float sE[16][64];
    int tid = threadIdx.x;
    for (int i = tid; i < 4096; i += 256) sK[i] = Kmat[i];
    __syncthreads();
    int c  = tid & 63;
    int rq = tid >> 6;            // 0..3 -> 4 rows each
    int nChunks = (N + 15) / 16;
    for (int chunk = blockIdx.x; chunk < nChunks; chunk += gridDim.x) {
        int n0 = chunk * 16;
        #pragma unroll
        for (int rr = 0; rr < 4; ++rr) {
            int r = rq * 4 + rr;
            int n = n0 + r;
            float v = 0.f;
            if (n < N) {
                size_t idx = (size_t)n * 64 + c;
                v = A[idx] + B1[idx] + B2[idx];
                E0[idx] = v;
            }
            sE[r][c] = v;
        }
        __syncthreads();
        float a0 = 0.f, a1 = 0.f, a2 = 0.f, a3 = 0.f;
        #pragma unroll
        for (int k = 0; k < 64; ++k) {
            float w = sK[k * 64 + c];
            a0 += sE[rq*4 + 0][k] * w;
            a1 += sE[rq*4 + 1][k] * w;
            a2 += sE[rq*4 + 2][k] * w;
            a3 += sE[rq*4 + 3][k] * w;
        }
        int h = c >> 4, j = c & 15;
        size_t kb = (size_t)h * N * 16 + j;
        int n;
        n = n0 + rq*4 + 0; if (n < N) Key[kb + (size_t)n * 16] = a0;
        n = n0 + rq*4 + 1; if (n < N) Key[kb + (size_t)n * 16] = a1;
        n = n0 + rq*4 + 2; if (n < N) Key[kb + (size_t)n * 16] = a2;
        n = n0 + rq*4 + 3; if (n < N) Key[kb + (size_t)n * 16] = a3;
        __syncthreads();
    }
}

// ---------------- fused: vp = cur@pV (per row) then VK[h,i,j] += vp[n,h*16+i]*Key[h,n,j] ----------------
__global__ void gemm_vk_kernel(const float* __restrict__ cur, const float* __restrict__ pV,
                               const float* __restrict__ Key, float* __restrict__ VK, int N)
{
    __shared__ float  sPV[4096];
    __shared__ float4 sE4[16][16];
    __shared__ float4 sKy4[16][16];
    __shared__ float  sVP[16][64];
    float* sE  = (float*)sE4;
    float* sKy = (float*)sKy4;
    int tid = threadIdx.x;
    for (int i = tid; i < 4096; i += 256) sPV[i] = pV[i];
    int c  = tid & 63;
    int rq = tid >> 6;
    int ii = (tid >> 4) & 15;
    int jj = tid & 15;
    float a0 = 0.f, a1 = 0.f, a2 = 0.f, a3 = 0.f;   // VK[h=0..3, ii, jj]
    __syncthreads();
    int nChunks = (N + 15) / 16;
    for (int chunk = blockIdx.x; chunk < nChunks; chunk += gridDim.x) {
        int n0 = chunk * 16;
        {   // load 16 rows of cur (float4)
            int r = tid >> 4, q = tid & 15;
            int n = n0 + r;
            float4 v = make_float4(0.f, 0.f, 0.f, 0.f);
            if (n < N) v = __ldg(((const float4*)cur) + (size_t)n * 16 + q);
            sE4[r][q] = v;
        }
        {   // load 16 rows of Key (float4): q = h*4 + j4
            int r = tid >> 4, q = tid & 15;
            int h = q >> 2, j4 = q & 3;
            int n = n0 + r;
            float4 v = make_float4(0.f, 0.f, 0.f, 0.f);
            if (n < N) v = __ldg(((const float4*)Key) + ((size_t)h * N + n) * 4 + j4);
            sKy4[r][q] = v;
        }
        __syncthreads();
        // vp[r][c] for 4 rows per thread
        float b0 = 0.f, b1 = 0.f, b2 = 0.f, b3 = 0.f;
        #pragma unroll
        for (int k = 0; k < 64; ++k) {
            float w = sPV[k * 64 + c];
            b0 += sE[(rq*4 + 0) * 64 + k] * w;
            b1 += sE[(rq*4 + 1) * 64 + k] * w;
            b2 += sE[(rq*4 + 2) * 64 + k] * w;
            b3 += sE[(rq*4 + 3) * 64 + k] * w;
        }
        sVP[rq*4 + 0][c] = b0;
        sVP[rq*4 + 1][c] = b1;
        sVP[rq*4 + 2][c] = b2;
        sVP[rq*4 + 3][c] = b3;
        __syncthreads();
        #pragma unroll
        for (int r = 0; r < 16; ++r) {
            a0 += sVP[r][ 0 + ii] * sKy[r * 64 +  0 + jj];
            a1 += sVP[r][16 + ii] * sKy[r * 64 + 16 + jj];
            a2 += sVP[r][32 + ii] * sKy[r * 64 + 32 + jj];
            a3 += sVP[r][48 + ii] * sKy[r * 64 + 48 + jj];
        }
        __syncthreads();
    }
    atomicAdd(&VK[      tid], a0);
    atomicAdd(&VK[256 + tid], a1);
    atomicAdd(&VK[512 + tid], a2);
    atomicAdd(&VK[768 + tid], a3);
}

__device__ __forceinline__ float leaky_f(float x) { return (x >= 0.f) ? x : 0.5f * x; }

// ---------------- t1 = (VK@hyp) ; t2 = leaky(t1@W1^T)+t1 (k-slice per block) ----------------
__global__ void t1t2_kernel(const float* __restrict__ VK, const float* __restrict__ Hyper,
                            const float* __restrict__ W1, float* __restrict__ T2out)
{
    __shared__ float sVK[1024];
    __shared__ float sT1[DDIM * HNN];
    int tid = threadIdx.x;
    for (int i = tid; i < 1024; i += 256) sVK[i] = VK[i];
    __syncthreads();
    for (int o = tid; o < 8192; o += 256) {
        int d = o >> 7, k = o & 127;
        int h = d >> 4, i = d & 15;
        float s = 0.f;
        #pragma unroll
        for (int j = 0; j < 16; ++j)
            s += sVK[h * 256 + i * 16 + j] * __ldg(&Hyper[k * 64 + h * 16 + j]);
        sT1[d * 128 + k] = s;
    }
    __syncthreads();
    int kb = blockIdx.x * 8;
    for (int o = tid; o < 512; o += 256) {
        int d = o >> 3, k = kb + (o & 7);
        float s = 0.f;
        #pragma unroll 8
        for (int m = 0; m < 128; ++m) s += sT1[d * 128 + m] * __ldg(&W1[k * 128 + m]);
        T2out[d * 128 + k] = leaky_f(s) + sT1[d * 128 + k];
    }
}

// ---------------- t3 = leaky(t2@W2^T)+t2 ----------------
__global__ void t3_kernel(const float* __restrict__ T2, const float* __restrict__ W2,
                          float* __restrict__ T3out)
{
    __shared__ float sT2[DDIM * HNN];
    int tid = threadIdx.x;
    for (int i = tid; i < 8192; i += 256) sT2[i] = T2[i];
    __syncthreads();
    int kb = blockIdx.x * 8;
    for (int o = tid; o < 512; o += 256) {
        int d = o >> 3, k = kb + (o & 7);
        float s = 0.f;
        #pragma unroll 8
        for (int m = 0; m < 128; ++m) s += sT2[d * 128 + m] * __ldg(&W2[k * 128 + m]);
        T3out[d * 128 + k] = leaky_f(s) + sT2[d * 128 + k];
    }
}

// ---------------- pre[h,i,j] = sum_k Hyper[k,h*16+i] * (sum_d t3[d,k]*V[d,h*16+j]) ----------------
__global__ void pre_kernel(const float* __restrict__ T3, const float* __restrict__ V,
                           const float* __restrict__ Hyper, float* __restrict__ PRE)
{
    __shared__ float sP0[16][64];
    __shared__ float sT3[16][64];
    __shared__ float sV[4096];
    int tid = threadIdx.x;
    int kb = blockIdx.x * 16;
    for (int i = tid; i < 4096; i += 256) sV[i] = V[i];
    for (int i = tid; i < 1024; i += 256) {
        int kk = i >> 6, d = i & 63;
        sT3[kk][d] = T3[d * 128 + kb + kk];
    }
    __syncthreads();
    for (int o = tid; o < 1024; o += 256) {
        int kk = o >> 6, d2 = o & 63;
        float s = 0.f;
        #pragma unroll
        for (int d = 0; d < 64; ++d) s += sT3[kk][d] * sV[d * 64 + d2];
        sP0[kk][d2] = s;
    }
    __syncthreads();
    for (int o = tid; o < 1024; o += 256) {
        int h = o >> 8, i = (o >> 4) & 15, j = o & 15;
        float s = 0.f;
        #pragma unroll
        for (int kk = 0; kk < 16; ++kk)
            s += __ldg(&Hyper[(size_t)(kb + kk) * 64 + h * 16 + i]) * sP0[kk][h * 16 + j];
        atomicAdd(&PRE[o], s);
    }
}

// ---------------- new[n,h*16+j] = sum_i Key[h,n,i]*pre[h,i,j]; cur=new; lat (+)= new ----------------
__global__ void newtotal_kernel(const float* __restrict__ Key, const float* __restrict__ PRE,
                                const float* __restrict__ E0, float* __restrict__ lat,
                                float* __restrict__ cur, int N, int first)
{
    __shared__ float sPre[1024];
    int tid = threadIdx.x;
    for (int i = tid; i < 1024; i += 256) sPre[i] = PRE[i];
    __syncthreads();
    int n = blockIdx.x * 64 + (tid & 63);
    int h = tid >> 6;
    if (n >= N) return;
    const float4* kp = (const float4*)Key + ((size_t)h * N + n) * 4;
    float4 k0 = __ldg(kp + 0), k1 = __ldg(kp + 1), k2 = __ldg(kp + 2), k3 = __ldg(kp + 3);
    float kv[16] = {k0.x,k0.y,k0.z,k0.w, k1.x,k1.y,k1.z,k1.w,
                    k2.x,k2.y,k2.z,k2.w, k3.x,k3.y,k3.z,k3.w};
    const float* pb = &sPre[h * 256];
    float o[16];
    #pragma unroll
    for (int j = 0; j < 16; ++j) {
        float s = 0.f;
        #pragma unroll
        for (int i = 0; i < 16; ++i) s += kv[i] * pb[i * 16 + j];
        o[j] = s;
    }
    size_t base = (size_t)n * 64 + h * 16;
    float4* cp = (float4*)(cur + base);
    cp[0] = make_float4(o[0], o[1], o[2],  o[3]);
    cp[1] = make_float4(o[4], o[5], o[6],  o[7]);
    cp[2] = make_float4(o[8], o[9], o[10], o[11]);
    cp[3] = make_float4(o[12],o[13],o[14], o[15]);
    float4* lp = (float4*)(lat + base);
    if (first) {
        const float4* ep = (const float4*)(E0 + base);
        #pragma unroll
        for (int q = 0; q < 4; ++q) {
            float4 e = __ldg(ep + q);
            lp[q] = make_float4(e.x + o[q*4+0], e.y + o[q*4+1], e.z + o[q*4+2], e.w + o[q*4+3]);
        }
    } else {
        #pragma unroll
        for (int q = 0; q < 4; ++q) {
            float4 e = lp[q];
            lp[q] = make_float4(e.x + o[q*4+0], e.y + o[q*4+1], e.z + o[q*4+2], e.w + o[q*4+3]);
        }
    }
}

// ---------------- host launch ----------------
extern "C" void kernel_launch(void* const* d_in, const int* in_sizes, int n_in,
                              void* d_out, int out_size)
{
    (void)in_sizes; (void)n_in; (void)out_size;
    const float* uE  = (const float*)d_in[0];
    const float* iE  = (const float*)d_in[1];
    const float* Ks  = (const float*)d_in[2];   // [3,64,64]
    const float* Hyp = (const float*)d_in[3];   // [3,128,64]
    const float* Vm  = (const float*)d_in[4];   // [3,64,64]
    const float* pVm = (const float*)d_in[5];   // [3,64,64]
    const float* W1  = (const float*)d_in[6];   // [3,2,128,128]
    const float* W2  = (const float*)d_in[7];   // [3,2,128,128]
    float* out = (float*)d_out;

    float *bTU1, *bTU2, *bTI1, *bTI2, *bUU1, *bUU2, *cur, *t2b, *t3b, *scr;
    cudaGetSymbolAddress((void**)&bTU1, g_bufTU1);
    cudaGetSymbolAddress((void**)&bTU2, g_bufTU2);
    cudaGetSymbolAddress((void**)&bTI1, g_bufTI1);
    cudaGetSymbolAddress((void**)&bTI2, g_bufTI2);
    cudaGetSymbolAddress((void**)&bUU1, g_bufUU1);
    cudaGetSymbolAddress((void**)&bUU2, g_bufUU2);
    cudaGetSymbolAddress((void**)&cur,  g_curbuf);
    cudaGetSymbolAddress((void**)&t2b,  g_t2buf);
    cudaGetSymbolAddress((void**)&t3b,  g_t3buf);
    cudaGetSymbolAddress((void**)&scr,  g_scrbuf);

    // output offsets (floats)
    float* O_uE0   = out + 0;
    float* O_iE0   = out + 6400000;
    float* O_ulat  = out + 9600000;
    float* O_ilat  = out + 16000000;
    float* O_uKey  = out + 19200000;
    float* O_iKey  = out + 25600000;
    float* O_uHyp  = out + 28800000;
    float* O_iHyp  = out + 28808192;
    float* O_uuE0  = out + 28816384;
    float* O_uulat = out + 35216384;
    float* O_uuKey = out + 41616384;
    float* O_uuHyp = out + 48016384;

    route_kernel<<<1, 1>>>(d_in[8], d_in[9], d_in[10], d_in[11], d_in[12],
                           d_in[13], d_in[14], d_in[15], d_in[16]);

    cudaMemsetAsync(bTU1, 0, sizeof(float) * (size_t)UN * DDIM, 0);
    cudaMemsetAsync(bTU2, 0, sizeof(float) * (size_t)UN * DDIM, 0);
    cudaMemsetAsync(bTI1, 0, sizeof(float) * (size_t)INUM * DDIM, 0);
    cudaMemsetAsync(bTI2, 0, sizeof(float) * (size_t)INUM * DDIM, 0);
    cudaMemsetAsync(bUU1, 0, sizeof(float) * (size_t)UN * DDIM, 0);
    cudaMemsetAsync(bUU2, 0, sizeof(float) * (size_t)UN * DDIM, 0);

    const int spmmGrid = (NNZE * 16) / 256;   // 62500
    spmm_kernel<<<spmmGrid, 256>>>(0, iE,   bTU1);   // tu1 = A  @ iE
    spmm_kernel<<<spmmGrid, 256>>>(1, uE,   bTI1);   // ti1 = A^T@ uE
    spmm_kernel<<<spmmGrid, 256>>>(2, uE,   bUU1);   // uu1 = S  @ uE
    spmm_kernel<<<spmmGrid, 256>>>(0, bTI1, bTU2);   // tu2 = A  @ ti1
    spmm_kernel<<<spmmGrid, 256>>>(1, bTU1, bTI2);   // ti2 = A^T@ tu1
    spmm_kernel<<<spmmGrid, 256>>>(2, bUU1, bUU2);   // uu2 = S  @ uu1

    embed_key_kernel<<<1480, 256>>>(uE, bTU1, bTU2, Ks + 0,    O_uE0,  O_uKey,  UN);
    embed_key_kernel<<<1480, 256>>>(iE, bTI1, bTI2, Ks + 4096, O_iE0,  O_iKey,  INUM);
    embed_key_kernel<<<1480, 256>>>(uE, bUU1, bUU2, Ks + 8192, O_uuE0, O_uuKey, UN);

    cudaMemcpyAsync(O_uHyp,  Hyp,          8192 * sizeof(float), cudaMemcpyDeviceToDevice, 0);
    cudaMemcpyAsync(O_iHyp,  Hyp + 8192,   8192 * sizeof(float), cudaMemcpyDeviceToDevice, 0);
    cudaMemcpyAsync(O_uuHyp, Hyp + 16384,  8192 * sizeof(float), cudaMemcpyDeviceToDevice, 0);

    struct TSpec { const float* E0; const float* Key; float* lat; int N; };
    TSpec T[3] = {
        { O_uE0,  O_uKey,  O_ulat,  UN   },
        { O_iE0,  O_iKey,  O_ilat,  INUM },
        { O_uuE0, O_uuKey, O_uulat, UN   },
    };

    for (int t = 0; t < 3; ++t) {
        const float* pV_t  = pVm + t * 4096;
        const float* V_t   = Vm  + t * 4096;
        const float* Hyp_t = Hyp + t * 8192;
        for (int l = 0; l < 2; ++l) {
            const float* W1_tl = W1 + (size_t)(t * 2 + l) * 16384;
            const float* W2_tl = W2 + (size_t)(t * 2 + l) * 16384;
            cudaMemsetAsync(scr, 0, 2048 * sizeof(float), 0);
            const float* curp = (l == 0) ? T[t].E0 : cur;
            gemm_vk_kernel<<<1480, 256>>>(curp, pV_t, T[t].Key, scr, T[t].N);
            t1t2_kernel<<<16, 256>>>(scr, Hyp_t, W1_tl, t2b);
            t3_kernel<<<16, 256>>>(t2b, W2_tl, t3b);
            pre_kernel<<<8, 256>>>(t3b, V_t, Hyp_t, scr + 1024);
            newtotal_kernel<<<(T[t].N + 63) / 64, 256>>>(T[t].Key, scr + 1024, T[t].E0,
                                                         T[t].lat, cur, T[t].N, (l == 0) ? 1 : 0);
        }
    }
}

// round 5
// speedup vs baseline: 1.1993x; 1.1993x over previous
#include <cuda_runtime.h>

// ---------------- problem constants ----------------
#define UN   100000
#define INUM 50000
#define NNZE 1000000

// ---------------- routed sparse pointers ----------------
__device__ const int*   g_rows[3];
__device__ const int*   g_cols[3];
__device__ const float* g_vals[3];

// ---------------- zeroed scratch (one memset per replay) ----------------
#define Z_TU1 0
#define Z_TU2 6400000
#define Z_UU1 12800000
#define Z_UU2 19200000
#define Z_TI1 25600000
#define Z_TI2 28800000
#define Z_SCR 32000000            // per transformer t: VK0 at t*4096, VK1 at +1024, pre0 at +2048, pre1 at +3072
#define Z_TOT 32012288
__device__ float g_z[Z_TOT];
__device__ float g_t2[8192];      // not zeroed (fully written each use)

// ---------------- router: detect metadata ordering of the 9 sparse arrays ----------------
__global__ void route_kernel(const void* a8, const void* a9, const void* a10,
                             const void* a11, const void* a12, const void* a13,
                             const void* a14, const void* a15, const void* a16)
{
    const unsigned* p = (const unsigned*)a8;
    unsigned m = 0;
    for (int i = 0; i < 32; ++i) { unsigned v = p[i]; m = (v > m) ? v : m; }
    if (m > 0x01000000u) {
        // signature order: vals first
        g_vals[0] = (const float*)a8;  g_vals[1] = (const float*)a9;  g_vals[2] = (const float*)a10;
        g_rows[0] = (const int*)a11;   g_cols[0] = (const int*)a12;
        g_rows[1] = (const int*)a13;   g_cols[1] = (const int*)a14;
        g_rows[2] = (const int*)a15;   g_cols[2] = (const int*)a16;
    } else {
        // dict order
        g_rows[0] = (const int*)a8;   g_cols[0] = (const int*)a9;   g_vals[0] = (const float*)a10;
        g_rows[1] = (const int*)a11;  g_cols[1] = (const int*)a12;  g_vals[1] = (const float*)a13;
        g_rows[2] = (const int*)a14;  g_cols[2] = (const int*)a15;  g_vals[2] = (const float*)a16;
    }
}

// ---------------- 3 SpMMs fused in one launch (16 lanes per nnz, float4 gather + v4 RED) ----------------
__global__ void spmm3_kernel(const float* __restrict__ X0, const float* __restrict__ X1,
                             const float* __restrict__ X2,
                             float* __restrict__ O0, float* __restrict__ O1, float* __restrict__ O2)
{
    int t = blockIdx.x * 256 + threadIdx.x;
    int eg = t >> 4;                      // global nnz id, 0..3*NNZE-1 (grid sized exactly)
    int which = (eg >= 2 * NNZE) ? 2 : ((eg >= NNZE) ? 1 : 0);   // uniform per block
    int e = eg - which * NNZE;
    int lane = t & 15;
    const float* X = (which == 0) ? X0 : ((which == 1) ? X1 : X2);
    float*       O = (which == 0) ? O0 : ((which == 1) ? O1 : O2);
    int   r = __ldg(&g_rows[which][e]);
    int   c = __ldg(&g_cols[which][e]);
    float v = __ldg(&g_vals[which][e]);
    float4 x = __ldg((const float4*)X + (size_t)c * 16 + lane);
    float* p = O + (size_t)r * 64 + lane * 4;
    asm volatile("red.global.add.v4.f32 [%0], {%1, %2, %3, %4};"
                 :: "l"(p), "f"(v * x.x), "f"(v * x.y), "f"(v * x.z), "f"(v * x.w) : "memory");
}

// ---------------- copy the 3 Hyper outputs in one launch ----------------
__global__ void copy_hyper_kernel(const float* __restrict__ Hyp,
                                  float* o0, float* o1, float* o2)
{
    int i = blockIdx.x * 256 + threadIdx.x;
    if (i < 8192) { o0[i] = Hyp[i]; o1[i] = Hyp[8192 + i]; o2[i] = Hyp[16384 + i]; }
}

// ---------------- fused embed+key+vp+Gram ----------------
// E0 = A+B1+B2 ; Key[h,n,j] = E0@K ; vp = E0@pV ; VK[h,i,j] += vp[n,h16+i]*Key[h,n,j]
// dynamic smem layout (floats): sK[4096] | sPV[4096] | sE[32*65] | sKy[32*65] | sVP[32*65]
__global__ void __launch_bounds__(256) embed_key_vk_kernel(
    const float* __restrict__ A, const float* __restrict__ B1, const float* __restrict__ B2,
    const float* __restrict__ Kmat, const float* __restrict__ pV,
    float* __restrict__ E0, float* __restrict__ Key, float* __restrict__ VK, int N)
{
    extern __shared__ float sm[];
    float* sK  = sm;
    float* sPV = sm + 4096;
    float* sE  = sm + 8192;          // [32][65]
    float* sKy = sE + 32 * 65;       // [32][65]
    float* sVP = sKy + 32 * 65;      // [32][65]
    int tid = threadIdx.x;
    for (int i = tid; i < 4096; i += 256) { sK[i] = Kmat[i]; sPV[i] = pV[i]; }
    int rq = tid >> 5;               // 0..7  -> rows rq*4..+3
    int tx = tid & 31;
    int c0 = tx, c1 = tx + 32;       // two cols, 32 apart (conflict-free LDS)
    int hg = tid >> 6, pi = (tid >> 3) & 7, pj = tid & 7;   // Gram 2x2-per-head mapping
    float g00 = 0.f, g01 = 0.f, g10 = 0.f, g11 = 0.f;
    __syncthreads();
    int nChunks = (N + 31) >> 5;
    for (int chunk = blockIdx.x; chunk < nChunks; chunk += gridDim.x) {
        int n0 = chunk << 5;
        #pragma unroll
        for (int q = 0; q < 2; ++q) {
            int idx = tid + q * 256;         // float4 index 0..511
            int r = idx >> 4, cc = idx & 15;
            int n = n0 + r;
            float4 v = make_float4(0.f, 0.f, 0.f, 0.f);
            if (n < N) {
                float4 a = __ldg((const float4*)A  + (size_t)n * 16 + cc);
                float4 b = __ldg((const float4*)B1 + (size_t)n * 16 + cc);
                float4 d = __ldg((const float4*)B2 + (size_t)n * 16 + cc);
                v = make_float4(a.x + b.x + d.x, a.y + b.y + d.y,
                                a.z + b.z + d.z, a.w + b.w + d.w);
                ((float4*)E0)[(size_t)n * 16 + cc] = v;
            }
            sE[r * 65 + cc * 4 + 0] = v.x; sE[r * 65 + cc * 4 + 1] = v.y;
            sE[r * 65 + cc * 4 + 2] = v.z; sE[r * 65 + cc * 4 + 3] = v.w;
        }
        __syncthreads();
        float ka[4][2] = {{0.f,0.f},{0.f,0.f},{0.f,0.f},{0.f,0.f}};
        float pa[4][2] = {{0.f,0.f},{0.f,0.f},{0.f,0.f},{0.f,0.f}};
        #pragma unroll 16
        for (int k = 0; k < 64; ++k) {
            float w0 = sK[k * 64 + c0],  w1 = sK[k * 64 + c1];
            float p0 = sPV[k * 64 + c0], p1 = sPV[k * 64 + c1];
            #pragma unroll
            for (int rr = 0; rr < 4; ++rr) {
                float e = sE[(rq * 4 + rr) * 65 + k];
                ka[rr][0] += e * w0; ka[rr][1] += e * w1;
                pa[rr][0] += e * p0; pa[rr][1] += e * p1;
            }
        }
        int h0 = c0 >> 4, j0 = c0 & 15, h1 = c1 >> 4, j1 = c1 & 15;
        size_t kb0 = (size_t)h0 * N * 16, kb1 = (size_t)h1 * N * 16;
        #pragma unroll
        for (int rr = 0; rr < 4; ++rr) {
            int rrow = rq * 4 + rr;
            sKy[rrow * 65 + c0] = ka[rr][0]; sKy[rrow * 65 + c1] = ka[rr][1];
            sVP[rrow * 65 + c0] = pa[rr][0]; sVP[rrow * 65 + c1] = pa[rr][1];
            int n = n0 + rrow;
            if (n < N) {
                Key[kb0 + (size_t)n * 16 + j0] = ka[rr][0];
                Key[kb1 + (size_t)n * 16 + j1] = ka[rr][1];
            }
        }
        __syncthreads();
        int ca0 = hg * 16 + 2 * pi, cb0 = hg * 16 + 2 * pj;
        #pragma unroll
        for (int r = 0; r < 32; ++r) {
            float va0 = sVP[r * 65 + ca0], va1 = sVP[r * 65 + ca0 + 1];
            float vb0 = sKy[r * 65 + cb0], vb1 = sKy[r * 65 + cb0 + 1];
            g00 += va0 * vb0; g01 += va0 * vb1;
            g10 += va1 * vb0; g11 += va1 * vb1;
        }
        __syncthreads();
    }
    atomicAdd(&VK[hg * 256 + (2 * pi    ) * 16 + 2 * pj    ], g00);
    atomicAdd(&VK[hg * 256 + (2 * pi    ) * 16 + 2 * pj + 1], g01);
    atomicAdd(&VK[hg * 256 + (2 * pi + 1) * 16 + 2 * pj    ], g10);
    atomicAdd(&VK[hg * 256 + (2 * pi + 1) * 16 + 2 * pj + 1], g11);
}

__device__ __forceinline__ float leaky_f(float x) { return (x >= 0.f) ? x : 0.5f * x; }

// ---------------- t1 = VK@hyp ; t2 = leaky(t1@W1^T)+t1 ----------------
__global__ void t1t2_kernel(const float* __restrict__ VK, const float* __restrict__ Hyper,
                            const float* __restrict__ W1, float* __restrict__ T2out)
{
    __shared__ float sVK[1024];
    __shared__ float sT1[8192];
    int tid = threadIdx.x;
    for (int i = tid; i < 1024; i += 256) sVK[i] = VK[i];
    __syncthreads();
    for (int o = tid; o < 8192; o += 256) {
        int d = o >> 7, k = o & 127;
        int h = d >> 4, i = d & 15;
        float s = 0.f;
        #pragma unroll
        for (int j = 0; j < 16; ++j)
            s += sVK[h * 256 + i * 16 + j] * __ldg(&Hyper[k * 64 + h * 16 + j]);
        sT1[d * 128 + k] = s;
    }
    __syncthreads();
    int kb = blockIdx.x * 8;
    for (int o = tid; o < 512; o += 256) {
        int d = o >> 3, k = kb + (o & 7);
        float s = 0.f;
        #pragma unroll 8
        for (int m = 0; m < 128; ++m) s += sT1[d * 128 + m] * __ldg(&W1[k * 128 + m]);
        T2out[d * 128 + k] = leaky_f(s) + sT1[d * 128 + k];
    }
}

// ---------------- fused t3+pre: t3 = leaky(t2@W2^T)+t2 ; pre += Hyper-weighted (t3^T@V), k-sliced ----------------
__global__ void t3pre_kernel(const float* __restrict__ T2, const float* __restrict__ W2,
                             const float* __restrict__ V, const float* __restrict__ Hyper,
                             float* __restrict__ PRE)
{
    __shared__ float sT2[8192];
    __shared__ float sT3[8][64];
    __shared__ float sP0[8][64];
    int tid = threadIdx.x;
    for (int i = tid; i < 8192; i += 256) sT2[i] = T2[i];
    __syncthreads();
    int kb = blockIdx.x * 8;
    for (int o = tid; o < 512; o += 256) {
        int d = o >> 3, kk = o & 7, k = kb + kk;
        float s = 0.f;
        #pragma unroll 8
        for (int m = 0; m < 128; ++m) s += sT2[d * 128 + m] * __ldg(&W2[k * 128 + m]);
        sT3[kk][d] = leaky_f(s) + sT2[d * 128 + k];
    }
    __syncthreads();
    for (int o = tid; o < 512; o += 256) {
        int kk = o >> 6, d2 = o & 63;
        float s = 0.f;
        #pragma unroll 8
        for (int d = 0; d < 64; ++d) s += sT3[kk][d] * __ldg(&V[d * 64 + d2]);
        sP0[kk][d2] = s;
    }
    __syncthreads();
    for (int o = tid; o < 1024; o += 256) {
        int h = o >> 8, i = (o >> 4) & 15, j = o & 15;
        float s = 0.f;
        #pragma unroll
        for (int kk = 0; kk < 8; ++kk)
            s += __ldg(&Hyper[(size_t)(kb + kk) * 64 + h * 16 + i]) * sP0[kk][h * 16 + j];
        atomicAdd(&PRE[o], s);
    }
}

// ---------------- layer-0 epilogue fused with layer-1 prologue ----------------
// new = Key@pre ; lat = E0+new ; vp = new@pV ; VKnext += vp^T x Key (per head)
// dynamic smem (floats): sPre[1024] | sPV[4096] | sNew[64*65] | sKy[64*65] | sVP[64*65]
__global__ void __launch_bounds__(256) newtotal_vk_kernel(
    const float* __restrict__ Key, const float* __restrict__ PRE,
    const float* __restrict__ E0, float* __restrict__ lat,
    const float* __restrict__ pV, float* __restrict__ VK, int N)
{
    extern __shared__ float sm[];
    float* sPre = sm;
    float* sPV  = sm + 1024;
    float* sNew = sm + 5120;             // [64][65]
    float* sKy  = sNew + 64 * 65;
    float* sVP  = sKy + 64 * 65;
    int tid = threadIdx.x;
    for (int i = tid; i < 1024; i += 256) sPre[i] = PRE[i];
    for (int i = tid; i < 4096; i += 256) sPV[i] = pV[i];
    __syncthreads();
    int nl = tid & 63, h = tid >> 6;
    int n = blockIdx.x * 64 + nl;
    bool valid = (n < N);
    float kv[16];
    #pragma unroll
    for (int i = 0; i < 16; ++i) kv[i] = 0.f;
    if (valid) {
        const float4* kp = (const float4*)Key + ((size_t)h * N + n) * 4;
        float4 k0 = __ldg(kp), k1 = __ldg(kp + 1), k2 = __ldg(kp + 2), k3 = __ldg(kp + 3);
        kv[0]=k0.x; kv[1]=k0.y; kv[2]=k0.z; kv[3]=k0.w;
        kv[4]=k1.x; kv[5]=k1.y; kv[6]=k1.z; kv[7]=k1.w;
        kv[8]=k2.x; kv[9]=k2.y; kv[10]=k2.z; kv[11]=k2.w;
        kv[12]=k3.x; kv[13]=k3.y; kv[14]=k3.z; kv[15]=k3.w;
    }
    const float* pb = &sPre[h * 256];
    float o[16];
    #pragma unroll
    for (int j = 0; j < 16; ++j) {
        float s = 0.f;
        #pragma unroll
        for (int i = 0; i < 16; ++i) s += kv[i] * pb[i * 16 + j];
        o[j] = s;
    }
    if (valid) {
        size_t base = (size_t)n * 64 + h * 16;
        const float4* ep = (const float4*)(E0 + base);
        float4* lp = (float4*)(lat + base);
        #pragma unroll
        for (int q = 0; q < 4; ++q) {
            float4 e = __ldg(ep + q);
            lp[q] = make_float4(e.x + o[q*4+0], e.y + o[q*4+1], e.z + o[q*4+2], e.w + o[q*4+3]);
        }
    }
    #pragma unroll
    for (int i = 0; i < 16; ++i) {
        sNew[nl * 65 + h * 16 + i] = o[i];
        sKy [nl * 65 + h * 16 + i] = kv[i];
    }
    __syncthreads();
    // vp = sNew @ pV, 4x4 register tile per thread
    {
        int ty = tid >> 4, tx = tid & 15, cb = tx * 4;
        float acc[4][4];
        #pragma unroll
        for (int a = 0; a < 4; ++a)
            #pragma unroll
            for (int b = 0; b < 4; ++b) acc[a][b] = 0.f;
        #pragma unroll 16
        for (int k = 0; k < 64; ++k) {
            float b0 = sPV[k * 64 + cb + 0], b1 = sPV[k * 64 + cb + 1];
            float b2 = sPV[k * 64 + cb + 2], b3 = sPV[k * 64 + cb + 3];
            #pragma unroll
            for (int a = 0; a < 4; ++a) {
                float av = sNew[(ty * 4 + a) * 65 + k];
                acc[a][0] += av * b0; acc[a][1] += av * b1;
                acc[a][2] += av * b2; acc[a][3] += av * b3;
            }
        }
        #pragma unroll
        for (int a = 0; a < 4; ++a)
            #pragma unroll
            for (int b = 0; b < 4; ++b)
                sVP[(ty * 4 + a) * 65 + cb + b] = acc[a][b];
    }
    __syncthreads();
    // Gram: VK[h,i,j] += sum_r vp[r][h16+i]*key[r][h16+j], 2x2 per head
    {
        int hg = tid >> 6, pi = (tid >> 3) & 7, pj = tid & 7;
        int ca0 = hg * 16 + 2 * pi, cb0 = hg * 16 + 2 * pj;
        float g00 = 0.f, g01 = 0.f, g10 = 0.f, g11 = 0.f;
        #pragma unroll 16
        for (int r = 0; r < 64; ++r) {
            float va0 = sVP[r * 65 + ca0], va1 = sVP[r * 65 + ca0 + 1];
            float vb0 = sKy[r * 65 + cb0], vb1 = sKy[r * 65 + cb0 + 1];
            g00 += va0 * vb0; g01 += va0 * vb1;
            g10 += va1 * vb0; g11 += va1 * vb1;
        }
        atomicAdd(&VK[hg * 256 + (2 * pi    ) * 16 + 2 * pj    ], g00);
        atomicAdd(&VK[hg * 256 + (2 * pi    ) * 16 + 2 * pj + 1], g01);
        atomicAdd(&VK[hg * 256 + (2 * pi + 1) * 16 + 2 * pj    ], g10);
        atomicAdd(&VK[hg * 256 + (2 * pi + 1) * 16 + 2 * pj + 1], g11);
    }
}

// ---------------- final layer epilogue: lat += Key@pre ----------------
__global__ void newtotal_final_kernel(const float* __restrict__ Key, const float* __restrict__ PRE,
                                      float* __restrict__ lat, int N)
{
    __shared__ float sPre[1024];
    int tid = threadIdx.x;
    for (int i = tid; i < 1024; i += 256) sPre[i] = PRE[i];
    __syncthreads();
    int n = blockIdx.x * 64 + (tid & 63);
    int h = tid >> 6;
    if (n >= N) return;
    const float4* kp = (const float4*)Key + ((size_t)h * N + n) * 4;
    float4 k0 = __ldg(kp), k1 = __ldg(kp + 1), k2 = __ldg(kp + 2), k3 = __ldg(kp + 3);
    float kv[16] = {k0.x,k0.y,k0.z,k0.w, k1.x,k1.y,k1.z,k1.w,
                    k2.x,k2.y,k2.z,k2.w, k3.x,k3.y,k3.z,k3.w};
    const float* pb = &sPre[h * 256];
    float o[16];
    #pragma unroll
    for (int j = 0; j < 16; ++j) {
        float s = 0.f;
        #pragma unroll
        for (int i = 0; i < 16; ++i) s += kv[i] * pb[i * 16 + j];
        o[j] = s;
    }
    size_t base = (size_t)n * 64 + h * 16;
    float4* lp = (float4*)(lat + base);
    #pragma unroll
    for (int q = 0; q < 4; ++q) {
        float4 e = lp[q];
        lp[q] = make_float4(e.x + o[q*4+0], e.y + o[q*4+1], e.z + o[q*4+2], e.w + o[q*4+3]);
    }
}

// ---------------- host launch ----------------
extern "C" void kernel_launch(void* const* d_in, const int* in_sizes, int n_in,
                              void* d_out, int out_size)
{
    (void)in_sizes; (void)n_in; (void)out_size;
    const float* uE  = (const float*)d_in[0];
    const float* iE  = (const float*)d_in[1];
    const float* Ks  = (const float*)d_in[2];   // [3,64,64]
    const float* Hyp = (const float*)d_in[3];   // [3,128,64]
    const float* Vm  = (const float*)d_in[4];   // [3,64,64]
    const float* pVm = (const float*)d_in[5];   // [3,64,64]
    const float* W1  = (const float*)d_in[6];   // [3,2,128,128]
    const float* W2  = (const float*)d_in[7];   // [3,2,128,128]
    float* out = (float*)d_out;

    float *z, *t2b;
    cudaGetSymbolAddress((void**)&z,   g_z);
    cudaGetSymbolAddress((void**)&t2b, g_t2);
    float* scrp = z + Z_SCR;

    static const int EMBED_SMEM = (4096 + 4096 + 3 * 32 * 65) * 4;   // 57728 B
    static const int NT_SMEM    = (1024 + 4096 + 3 * 64 * 65) * 4;   // 70400 B
    cudaFuncSetAttribute(embed_key_vk_kernel, cudaFuncAttributeMaxDynamicSharedMemorySize, EMBED_SMEM);
    cudaFuncSetAttribute(newtotal_vk_kernel,  cudaFuncAttributeMaxDynamicSharedMemorySize, NT_SMEM);

    // output offsets (floats)
    float* O_uE0   = out + 0;
    float* O_iE0   = out + 6400000;
    float* O_ulat  = out + 9600000;
    float* O_ilat  = out + 16000000;
    float* O_uKey  = out + 19200000;
    float* O_iKey  = out + 25600000;
    float* O_uHyp  = out + 28800000;
    float* O_iHyp  = out + 28808192;
    float* O_uuE0  = out + 28816384;
    float* O_uulat = out + 35216384;
    float* O_uuKey = out + 41616384;
    float* O_uuHyp = out + 48016384;

    route_kernel<<<1, 1>>>(d_in[8], d_in[9], d_in[10], d_in[11], d_in[12],
                           d_in[13], d_in[14], d_in[15], d_in[16]);
    cudaMemsetAsync(z, 0, (size_t)Z_TOT * sizeof(float), 0);

    // hop 1 (3 independent spmms in one launch), then hop 2
    const int spmmGrid = (3 * NNZE * 16) / 256;   // 187500
    spmm3_kernel<<<spmmGrid, 256>>>(iE, uE, uE, z + Z_TU1, z + Z_TI1, z + Z_UU1);
    spmm3_kernel<<<spmmGrid, 256>>>(z + Z_TI1, z + Z_TU1, z + Z_UU1,
                                    z + Z_TU2, z + Z_TI2, z + Z_UU2);

    copy_hyper_kernel<<<32, 256>>>(Hyp, O_uHyp, O_iHyp, O_uuHyp);

    // fused embed + key + layer-0 vp/Gram
    embed_key_vk_kernel<<<1480, 256, EMBED_SMEM>>>(uE, z + Z_TU1, z + Z_TU2, Ks + 0,
                                                   pVm + 0,    O_uE0,  O_uKey,  scrp + 0 * 4096, UN);
    embed_key_vk_kernel<<<1480, 256, EMBED_SMEM>>>(iE, z + Z_TI1, z + Z_TI2, Ks + 4096,
                                                   pVm + 4096, O_iE0,  O_iKey,  scrp + 1 * 4096, INUM);
    embed_key_vk_kernel<<<1480, 256, EMBED_SMEM>>>(uE, z + Z_UU1, z + Z_UU2, Ks + 8192,
                                                   pVm + 8192, O_uuE0, O_uuKey, scrp + 2 * 4096, UN);

    struct TSpec { const float* E0; const float* Key; float* lat; int N; };
    TSpec T[3] = {
        { O_uE0,  O_uKey,  O_ulat,  UN   },
        { O_iE0,  O_iKey,  O_ilat,  INUM },
        { O_uuE0, O_uuKey, O_uulat, UN   },
    };

    for (int t = 0; t < 3; ++t) {
        const float* pV_t  = pVm + t * 4096;
        const float* V_t   = Vm  + t * 4096;
        const float* Hyp_t = Hyp + t * 8192;
        float* VK0  = scrp + t * 4096;
        float* VK1  = VK0 + 1024;
        float* pre0 = VK0 + 2048;
        float* pre1 = VK0 + 3072;
        const float* W1_t0 = W1 + (size_t)(t * 2 + 0) * 16384;
        const float* W2_t0 = W2 + (size_t)(t * 2 + 0) * 16384;
        const float* W1_t1 = W1 + (size_t)(t * 2 + 1) * 16384;
        const float* W2_t1 = W2 + (size_t)(t * 2 + 1) * 16384;
        int nBlk = (T[t].N + 63) / 64;

        // layer 0
        t1t2_kernel<<<16, 256>>>(VK0, Hyp_t, W1_t0, t2b);
        t3pre_kernel<<<16, 256>>>(t2b, W2_t0, V_t, Hyp_t, pre0);
        newtotal_vk_kernel<<<nBlk, 256, NT_SMEM>>>(T[t].Key, pre0, T[t].E0, T[t].lat,
                                                   pV_t, VK1, T[t].N);
        // layer 1
        t1t2_kernel<<<16, 256>>>(VK1, Hyp_t, W1_t1, t2b);
        t3pre_kernel<<<16, 256>>>(t2b, W2_t1, V_t, Hyp_t, pre1);
        newtotal_final_kernel<<<nBlk, 256>>>(T[t].Key, pre1, T[t].lat, T[t].N);
    }
}

// round 6
// speedup vs baseline: 1.7155x; 1.4304x over previous
#include <cuda_runtime.h>

// ---------------- problem constants ----------------
#define UN   100000
#define INUM 50000
#define NNZE 1000000
#define NROWS_TOT (UN + INUM + UN)     // 250000

// ---------------- routed sparse pointers ----------------
__device__ const int*   g_rows[3];
__device__ const int*   g_cols[3];
__device__ const float* g_vals[3];

// ---------------- scratch ----------------
// zeroed each replay:
__device__ unsigned g_cnt[NROWS_TOT];          // 1MB
__device__ float    g_scr[3 * 4096];           // per t: VK0 +0, VK1 +1024, pre0 +2048, pre1 +3072
// fully rewritten each replay (no zeroing needed):
__device__ unsigned g_rowstart[NROWS_TOT + 3];
__device__ unsigned g_cursor[NROWS_TOT + 3];
__device__ unsigned long long g_csr[3 * NNZE]; // packed (val<<32 | col)
__device__ float    g_spbuf[32000000];         // TU1,TU2,UU1,UU2 (6.4M ea) + TI1,TI2 (3.2M ea)
__device__ float    g_t2[3 * 8192];

#define Z_TU1 0
#define Z_TU2 6400000
#define Z_UU1 12800000
#define Z_UU2 19200000
#define Z_TI1 25600000
#define Z_TI2 28800000

// ---------------- router: detect metadata ordering of the 9 sparse arrays ----------------
__global__ void route_kernel(const void* a8, const void* a9, const void* a10,
                             const void* a11, const void* a12, const void* a13,
                             const void* a14, const void* a15, const void* a16)
{
    const unsigned* p = (const unsigned*)a8;
    unsigned m = 0;
    for (int i = 0; i < 32; ++i) { unsigned v = p[i]; m = (v > m) ? v : m; }
    if (m > 0x01000000u) {
        g_vals[0] = (const float*)a8;  g_vals[1] = (const float*)a9;  g_vals[2] = (const float*)a10;
        g_rows[0] = (const int*)a11;   g_cols[0] = (const int*)a12;
        g_rows[1] = (const int*)a13;   g_cols[1] = (const int*)a14;
        g_rows[2] = (const int*)a15;   g_cols[2] = (const int*)a16;
    } else {
        g_rows[0] = (const int*)a8;   g_cols[0] = (const int*)a9;   g_vals[0] = (const float*)a10;
        g_rows[1] = (const int*)a11;  g_cols[1] = (const int*)a12;  g_vals[1] = (const float*)a13;
        g_rows[2] = (const int*)a14;  g_cols[2] = (const int*)a15;  g_vals[2] = (const float*)a16;
    }
}

// ---------------- CSR build: histogram ----------------
__global__ void hist3_kernel()
{
    int e = blockIdx.x * 256 + threadIdx.x;
    if (e >= 3 * NNZE) return;
    int m = (e >= 2 * NNZE) ? 2 : ((e >= NNZE) ? 1 : 0);
    int i = e - m * NNZE;
    int cb = (m == 0) ? 0 : ((m == 1) ? UN : UN + INUM);
    int r = __ldg(&g_rows[m][i]);
    atomicAdd(&g_cnt[cb + r], 1u);
}

// ---------------- CSR build: 3 exclusive scans (one block each) ----------------
__global__ void scan3_kernel()
{
    __shared__ unsigned sPart[1024];
    int m = blockIdx.x;
    int Nm  = (m == 1) ? INUM : UN;
    int cb  = (m == 0) ? 0 : ((m == 1) ? UN : UN + INUM);
    int rb  = (m == 0) ? 0 : ((m == 1) ? UN + 1 : UN + INUM + 2);
    int t = threadIdx.x;
    int chunk = (Nm + 1023) >> 10;
    int lo = t * chunk; if (lo > Nm) lo = Nm;
    int hi = lo + chunk; if (hi > Nm) hi = Nm;
    unsigned s = 0;
    for (int i = lo; i < hi; ++i) s += g_cnt[cb + i];
    sPart[t] = s;
    __syncthreads();
    for (int d = 1; d < 1024; d <<= 1) {
        unsigned v = (t >= d) ? sPart[t - d] : 0u;
        __syncthreads();
        sPart[t] += v;
        __syncthreads();
    }
    unsigned run = (t == 0) ? 0u : sPart[t - 1];
    for (int i = lo; i < hi; ++i) {
        unsigned c = g_cnt[cb + i];
        g_rowstart[rb + i] = run;
        g_cursor[rb + i]   = run;
        run += c;
    }
    if (t == 1023) g_rowstart[rb + Nm] = run;   // == NNZE
}

// ---------------- CSR build: scatter packed entries ----------------
__global__ void scatter3_kernel()
{
    int e = blockIdx.x * 256 + threadIdx.x;
    if (e >= 3 * NNZE) return;
    int m = (e >= 2 * NNZE) ? 2 : ((e >= NNZE) ? 1 : 0);
    int i = e - m * NNZE;
    int rb = (m == 0) ? 0 : ((m == 1) ? UN + 1 : UN + INUM + 2);
    int   r = __ldg(&g_rows[m][i]);
    int   c = __ldg(&g_cols[m][i]);
    float v = __ldg(&g_vals[m][i]);
    unsigned idx = atomicAdd(&g_cursor[rb + r], 1u);
    g_csr[(size_t)m * NNZE + idx] =
        ((unsigned long long)__float_as_uint(v) << 32) | (unsigned)c;
}

// ---------------- gather SpMM: 3 matrices, 16 lanes per row, no atomics ----------------
__global__ void __launch_bounds__(256) gather3_kernel(
    const float* __restrict__ X0, const float* __restrict__ X1, const float* __restrict__ X2,
    float* __restrict__ O0, float* __restrict__ O1, float* __restrict__ O2)
{
    int gr = blockIdx.x * 16 + (threadIdx.x >> 4);   // 0..249999
    int lane = threadIdx.x & 15;
    int m, r, rb;
    const float* X; float* O;
    if (gr < UN)              { m = 0; r = gr;             rb = 0;              X = X0; O = O0; }
    else if (gr < UN + INUM)  { m = 1; r = gr - UN;        rb = UN + 1;         X = X1; O = O1; }
    else                      { m = 2; r = gr - UN - INUM; rb = UN + INUM + 2;  X = X2; O = O2; }
    unsigned s = __ldg(&g_rowstart[rb + r]);
    unsigned e = __ldg(&g_rowstart[rb + r + 1]);
    const unsigned long long* csr = g_csr + (size_t)m * NNZE;
    float4 acc = make_float4(0.f, 0.f, 0.f, 0.f);
    unsigned i = s;
    for (; i + 2 <= e; i += 2) {
        unsigned long long u0 = __ldg(&csr[i]);
        unsigned long long u1 = __ldg(&csr[i + 1]);
        int   c0 = (int)(u0 & 0xffffffffu);
        float v0 = __uint_as_float((unsigned)(u0 >> 32));
        int   c1 = (int)(u1 & 0xffffffffu);
        float v1 = __uint_as_float((unsigned)(u1 >> 32));
        float4 x0 = __ldg((const float4*)X + (size_t)c0 * 16 + lane);
        float4 x1 = __ldg((const float4*)X + (size_t)c1 * 16 + lane);
        acc.x += v0 * x0.x; acc.y += v0 * x0.y; acc.z += v0 * x0.z; acc.w += v0 * x0.w;
        acc.x += v1 * x1.x; acc.y += v1 * x1.y; acc.z += v1 * x1.z; acc.w += v1 * x1.w;
    }
    if (i < e) {
        unsigned long long u0 = __ldg(&csr[i]);
        int   c0 = (int)(u0 & 0xffffffffu);
        float v0 = __uint_as_float((unsigned)(u0 >> 32));
        float4 x0 = __ldg((const float4*)X + (size_t)c0 * 16 + lane);
        acc.x += v0 * x0.x; acc.y += v0 * x0.y; acc.z += v0 * x0.z; acc.w += v0 * x0.w;
    }
    ((float4*)O)[(size_t)r * 16 + lane] = acc;
}

// ---------------- copy the 3 Hyper outputs ----------------
__global__ void copy_hyper_kernel(const float* __restrict__ Hyp,
                                  float* o0, float* o1, float* o2)
{
    int i = blockIdx.x * 256 + threadIdx.x;
    if (i < 8192) { o0[i] = Hyp[i]; o1[i] = Hyp[8192 + i]; o2[i] = Hyp[16384 + i]; }
}

// ---------------- fused embed+key+vp+Gram (layer-0 prologue) ----------------
__global__ void __launch_bounds__(256) embed_key_vk_kernel(
    const float* __restrict__ A, const float* __restrict__ B1, const float* __restrict__ B2,
    const float* __restrict__ Kmat, const float* __restrict__ pV,
    float* __restrict__ E0, float* __restrict__ Key, float* __restrict__ VK, int N)
{
    extern __shared__ float sm[];
    float* sK  = sm;
    float* sPV = sm + 4096;
    float* sE  = sm + 8192;          // [32][65]
    float* sKy = sE + 32 * 65;
    float* sVP = sKy + 32 * 65;
    int tid = threadIdx.x;
    for (int i = tid; i < 4096; i += 256) { sK[i] = Kmat[i]; sPV[i] = pV[i]; }
    int rq = tid >> 5;
    int tx = tid & 31;
    int c0 = tx, c1 = tx + 32;
    int hg = tid >> 6, pi = (tid >> 3) & 7, pj = tid & 7;
    float g00 = 0.f, g01 = 0.f, g10 = 0.f, g11 = 0.f;
    __syncthreads();
    int nChunks = (N + 31) >> 5;
    for (int chunk = blockIdx.x; chunk < nChunks; chunk += gridDim.x) {
        int n0 = chunk << 5;
        #pragma unroll
        for (int q = 0; q < 2; ++q) {
            int idx = tid + q * 256;
            int r = idx >> 4, cc = idx & 15;
            int n = n0 + r;
            float4 v = make_float4(0.f, 0.f, 0.f, 0.f);
            if (n < N) {
                float4 a = __ldg((const float4*)A  + (size_t)n * 16 + cc);
                float4 b = __ldg((const float4*)B1 + (size_t)n * 16 + cc);
                float4 d = __ldg((const float4*)B2 + (size_t)n * 16 + cc);
                v = make_float4(a.x + b.x + d.x, a.y + b.y + d.y,
                                a.z + b.z + d.z, a.w + b.w + d.w);
                ((float4*)E0)[(size_t)n * 16 + cc] = v;
            }
            sE[r * 65 + cc * 4 + 0] = v.x; sE[r * 65 + cc * 4 + 1] = v.y;
            sE[r * 65 + cc * 4 + 2] = v.z; sE[r * 65 + cc * 4 + 3] = v.w;
        }
        __syncthreads();
        float ka[4][2] = {{0.f,0.f},{0.f,0.f},{0.f,0.f},{0.f,0.f}};
        float pa[4][2] = {{0.f,0.f},{0.f,0.f},{0.f,0.f},{0.f,0.f}};
        #pragma unroll 16
        for (int k = 0; k < 64; ++k) {
            float w0 = sK[k * 64 + c0],  w1 = sK[k * 64 + c1];
            float p0 = sPV[k * 64 + c0], p1 = sPV[k * 64 + c1];
            #pragma unroll
            for (int rr = 0; rr < 4; ++rr) {
                float ev = sE[(rq * 4 + rr) * 65 + k];
                ka[rr][0] += ev * w0; ka[rr][1] += ev * w1;
                pa[rr][0] += ev * p0; pa[rr][1] += ev * p1;
            }
        }
        int h0 = c0 >> 4, j0 = c0 & 15, h1 = c1 >> 4, j1 = c1 & 15;
        size_t kb0 = (size_t)h0 * N * 16, kb1 = (size_t)h1 * N * 16;
        #pragma unroll
        for (int rr = 0; rr < 4; ++rr) {
            int rrow = rq * 4 + rr;
            sKy[rrow * 65 + c0] = ka[rr][0]; sKy[rrow * 65 + c1] = ka[rr][1];
            sVP[rrow * 65 + c0] = pa[rr][0]; sVP[rrow * 65 + c1] = pa[rr][1];
            int n = n0 + rrow;
            if (n < N) {
                Key[kb0 + (size_t)n * 16 + j0] = ka[rr][0];
                Key[kb1 + (size_t)n * 16 + j1] = ka[rr][1];
            }
        }
        __syncthreads();
        int ca0 = hg * 16 + 2 * pi, cb0 = hg * 16 + 2 * pj;
        #pragma unroll
        for (int r = 0; r < 32; ++r) {
            float va0 = sVP[r * 65 + ca0], va1 = sVP[r * 65 + ca0 + 1];
            float vb0 = sKy[r * 65 + cb0], vb1 = sKy[r * 65 + cb0 + 1];
            g00 += va0 * vb0; g01 += va0 * vb1;
            g10 += va1 * vb0; g11 += va1 * vb1;
        }
        __syncthreads();
    }
    atomicAdd(&VK[hg * 256 + (2 * pi    ) * 16 + 2 * pj    ], g00);
    atomicAdd(&VK[hg * 256 + (2 * pi    ) * 16 + 2 * pj + 1], g01);
    atomicAdd(&VK[hg * 256 + (2 * pi + 1) * 16 + 2 * pj    ], g10);
    atomicAdd(&VK[hg * 256 + (2 * pi + 1) * 16 + 2 * pj + 1], g11);
}

__device__ __forceinline__ float leaky_f(float x) { return (x >= 0.f) ? x : 0.5f * x; }

// ---------------- batched t1t2: all 3 transformers, one layer ----------------
__global__ void t1t2_all_kernel(const float* __restrict__ Hyp, const float* __restrict__ W1base,
                                int layer)
{
    __shared__ float sVK[1024];
    __shared__ float sT1[8192];
    int t = blockIdx.y;
    const float* VK    = g_scr + t * 4096 + layer * 1024;
    const float* Hyper = Hyp + t * 8192;
    const float* W1    = W1base + (size_t)(t * 2 + layer) * 16384;
    float* T2out       = g_t2 + t * 8192;
    int tid = threadIdx.x;
    for (int i = tid; i < 1024; i += 256) sVK[i] = VK[i];
    __syncthreads();
    for (int o = tid; o < 8192; o += 256) {
        int d = o >> 7, k = o & 127;
        int h = d >> 4, i = d & 15;
        float s = 0.f;
        #pragma unroll
        for (int j = 0; j < 16; ++j)
            s += sVK[h * 256 + i * 16 + j] * __ldg(&Hyper[k * 64 + h * 16 + j]);
        sT1[d * 128 + k] = s;
    }
    __syncthreads();
    int kb = blockIdx.x * 8;
    for (int o = tid; o < 512; o += 256) {
        int d = o >> 3, k = kb + (o & 7);
        float s = 0.f;
        #pragma unroll 8
        for (int m = 0; m < 128; ++m) s += sT1[d * 128 + m] * __ldg(&W1[k * 128 + m]);
        T2out[d * 128 + k] = leaky_f(s) + sT1[d * 128 + k];
    }
}

// ---------------- batched t3+pre ----------------
__global__ void t3pre_all_kernel(const float* __restrict__ W2base, const float* __restrict__ Vbase,
                                 const float* __restrict__ Hyp, int layer)
{
    __shared__ float sT2[8192];
    __shared__ float sT3[8][64];
    __shared__ float sP0[8][64];
    int t = blockIdx.y;
    const float* T2    = g_t2 + t * 8192;
    const float* W2    = W2base + (size_t)(t * 2 + layer) * 16384;
    const float* V     = Vbase + t * 4096;
    const float* Hyper = Hyp + t * 8192;
    float* PRE         = g_scr + t * 4096 + 2048 + layer * 1024;
    int tid = threadIdx.x;
    for (int i = tid; i < 8192; i += 256) sT2[i] = T2[i];
    __syncthreads();
    int kb = blockIdx.x * 8;
    for (int o = tid; o < 512; o += 256) {
        int d = o >> 3, kk = o & 7, k = kb + kk;
        float s = 0.f;
        #pragma unroll 8
        for (int m = 0; m < 128; ++m) s += sT2[d * 128 + m] * __ldg(&W2[k * 128 + m]);
        sT3[kk][d] = leaky_f(s) + sT2[d * 128 + k];
    }
    __syncthreads();
    for (int o = tid; o < 512; o += 256) {
        int kk = o >> 6, d2 = o & 63;
        float s = 0.f;
        #pragma unroll 8
        for (int d = 0; d < 64; ++d) s += sT3[kk][d] * __ldg(&V[d * 64 + d2]);
        sP0[kk][d2] = s;
    }
    __syncthreads();
    for (int o = tid; o < 1024; o += 256) {
        int h = o >> 8, i = (o >> 4) & 15, j = o & 15;
        float s = 0.f;
        #pragma unroll
        for (int kk = 0; kk < 8; ++kk)
            s += __ldg(&Hyper[(size_t)(kb + kk) * 64 + h * 16 + i]) * sP0[kk][h * 16 + j];
        atomicAdd(&PRE[o], s);
    }
}

// ---------------- batched layer-0 epilogue + layer-1 prologue ----------------
// new = Key@pre0 ; lat = E0+new ; vp = new@pV ; VK1 += vp^T x Key (per head)
__global__ void __launch_bounds__(256) newtotal_vk_all_kernel(
    const float* K0, const float* K1, const float* K2,
    const float* E0a, const float* E0b, const float* E0c,
    float* La, float* Lb, float* Lc,
    const float* __restrict__ pVbase)
{
    int t = blockIdx.y;
    int N = (t == 1) ? INUM : UN;
    if (blockIdx.x * 64 >= N) return;
    const float* Key = (t == 0) ? K0 : ((t == 1) ? K1 : K2);
    const float* E0  = (t == 0) ? E0a : ((t == 1) ? E0b : E0c);
    float* lat       = (t == 0) ? La : ((t == 1) ? Lb : Lc);
    const float* PRE = g_scr + t * 4096 + 2048;
    const float* pV  = pVbase + t * 4096;
    float* VK        = g_scr + t * 4096 + 1024;

    extern __shared__ float sm[];
    float* sPre = sm;
    float* sPV  = sm + 1024;
    float* sNew = sm + 5120;             // [64][65]
    float* sKy  = sNew + 64 * 65;
    float* sVP  = sKy + 64 * 65;
    int tid = threadIdx.x;
    for (int i = tid; i < 1024; i += 256) sPre[i] = PRE[i];
    for (int i = tid; i < 4096; i += 256) sPV[i] = pV[i];
    __syncthreads();
    int nl = tid & 63, h = tid >> 6;
    int n = blockIdx.x * 64 + nl;
    bool valid = (n < N);
    float kv[16];
    #pragma unroll
    for (int i = 0; i < 16; ++i) kv[i] = 0.f;
    if (valid) {
        const float4* kp = (const float4*)Key + ((size_t)h * N + n) * 4;
        float4 k0 = __ldg(kp), k1 = __ldg(kp + 1), k2 = __ldg(kp + 2), k3 = __ldg(kp + 3);
        kv[0]=k0.x; kv[1]=k0.y; kv[2]=k0.z; kv[3]=k0.w;
        kv[4]=k1.x; kv[5]=k1.y; kv[6]=k1.z; kv[7]=k1.w;
        kv[8]=k2.x; kv[9]=k2.y; kv[10]=k2.z; kv[11]=k2.w;
        kv[12]=k3.x; kv[13]=k3.y; kv[14]=k3.z; kv[15]=k3.w;
    }
    const float* pb = &sPre[h * 256];
    float o[16];
    #pragma unroll
    for (int j = 0; j < 16; ++j) {
        float s = 0.f;
        #pragma unroll
        for (int i = 0; i < 16; ++i) s += kv[i] * pb[i * 16 + j];
        o[j] = s;
    }
    if (valid) {
        size_t base = (size_t)n * 64 + h * 16;
        const float4* ep = (const float4*)(E0 + base);
        float4* lp = (float4*)(lat + base);
        #pragma unroll
        for (int q = 0; q < 4; ++q) {
            float4 e = __ldg(ep + q);
            lp[q] = make_float4(e.x + o[q*4+0], e.y + o[q*4+1], e.z + o[q*4+2], e.w + o[q*4+3]);
        }
    }
    #pragma unroll
    for (int i = 0; i < 16; ++i) {
        sNew[nl * 65 + h * 16 + i] = o[i];
        sKy [nl * 65 + h * 16 + i] = kv[i];
    }
    __syncthreads();
    {
        int ty = tid >> 4, tx = tid & 15, cb = tx * 4;
        float acc[4][4];
        #pragma unroll
        for (int a = 0; a < 4; ++a)
            #pragma unroll
            for (int b = 0; b < 4; ++b) acc[a][b] = 0.f;
        #pragma unroll 16
        for (int k = 0; k < 64; ++k) {
            float b0 = sPV[k * 64 + cb + 0], b1 = sPV[k * 64 + cb + 1];
            float b2 = sPV[k * 64 + cb + 2], b3 = sPV[k * 64 + cb + 3];
            #pragma unroll
            for (int a = 0; a < 4; ++a) {
                float av = sNew[(ty * 4 + a) * 65 + k];
                acc[a][0] += av * b0; acc[a][1] += av * b1;
                acc[a][2] += av * b2; acc[a][3] += av * b3;
            }
        }
        #pragma unroll
        for (int a = 0; a < 4; ++a)
            #pragma unroll
            for (int b = 0; b < 4; ++b)
                sVP[(ty * 4 + a) * 65 + cb + b] = acc[a][b];
    }
    __syncthreads();
    {
        int hg = tid >> 6, pi = (tid >> 3) & 7, pj = tid & 7;
        int ca0 = hg * 16 + 2 * pi, cb0 = hg * 16 + 2 * pj;
        float g00 = 0.f, g01 = 0.f, g10 = 0.f, g11 = 0.f;
        #pragma unroll 16
        for (int r = 0; r < 64; ++r) {
            float va0 = sVP[r * 65 + ca0], va1 = sVP[r * 65 + ca0 + 1];
            float vb0 = sKy[r * 65 + cb0], vb1 = sKy[r * 65 + cb0 + 1];
            g00 += va0 * vb0; g01 += va0 * vb1;
            g10 += va1 * vb0; g11 += va1 * vb1;
        }
        atomicAdd(&VK[hg * 256 + (2 * pi    ) * 16 + 2 * pj    ], g00);
        atomicAdd(&VK[hg * 256 + (2 * pi    ) * 16 + 2 * pj + 1], g01);
        atomicAdd(&VK[hg * 256 + (2 * pi + 1) * 16 + 2 * pj    ], g10);
        atomicAdd(&VK[hg * 256 + (2 * pi + 1) * 16 + 2 * pj + 1], g11);
    }
}

// ---------------- batched final epilogue: lat += Key@pre1 ----------------
__global__ void newtotal_final_all_kernel(const float* K0, const float* K1, const float* K2,
                                          float* La, float* Lb, float* Lc)
{
    int t = blockIdx.y;
    int N = (t == 1) ? INUM : UN;
    if (blockIdx.x * 64 >= N) return;
    const float* Key = (t == 0) ? K0 : ((t == 1) ? K1 : K2);
    float* lat       = (t == 0) ? La : ((t == 1) ? Lb : Lc);
    const float* PRE = g_scr + t * 4096 + 3072;
    __shared__ float sPre[1024];
    int tid = threadIdx.x;
    for (int i = tid; i < 1024; i += 256) sPre[i] = PRE[i];
    __syncthreads();
    int n = blockIdx.x * 64 + (tid & 63);
    int h = tid >> 6;
    if (n >= N) return;
    const float4* kp = (const float4*)Key + ((size_t)h * N + n) * 4;
    float4 k0 = __ldg(kp), k1 = __ldg(kp + 1), k2 = __ldg(kp + 2), k3 = __ldg(kp + 3);
    float kv[16] = {k0.x,k0.y,k0.z,k0.w, k1.x,k1.y,k1.z,k1.w,
                    k2.x,k2.y,k2.z,k2.w, k3.x,k3.y,k3.z,k3.w};
    const float* pb = &sPre[h * 256];
    float o[16];
    #pragma unroll
    for (int j = 0; j < 16; ++j) {
        float s = 0.f;
        #pragma unroll
        for (int i = 0; i < 16; ++i) s += kv[i] * pb[i * 16 + j];
        o[j] = s;
    }
    size_t base = (size_t)n * 64 + h * 16;
    float4* lp = (float4*)(lat + base);
    #pragma unroll
    for (int q = 0; q < 4; ++q) {
        float4 e = lp[q];
        lp[q] = make_float4(e.x + o[q*4+0], e.y + o[q*4+1], e.z + o[q*4+2], e.w + o[q*4+3]);
    }
}

// ---------------- host launch ----------------
extern "C" void kernel_launch(void* const* d_in, const int* in_sizes, int n_in,
                              void* d_out, int out_size)
{
    (void)in_sizes; (void)n_in; (void)out_size;
    const float* uE  = (const float*)d_in[0];
    const float* iE  = (const float*)d_in[1];
    const float* Ks  = (const float*)d_in[2];
    const float* Hyp = (const float*)d_in[3];
    const float* Vm  = (const float*)d_in[4];
    const float* pVm = (const float*)d_in[5];
    const float* W1  = (const float*)d_in[6];
    const float* W2  = (const float*)d_in[7];
    float* out = (float*)d_out;

    float *sp, *scrp; unsigned* cntp;
    cudaGetSymbolAddress((void**)&sp,   g_spbuf);
    cudaGetSymbolAddress((void**)&scrp, g_scr);
    cudaGetSymbolAddress((void**)&cntp, g_cnt);

    static const int EMBED_SMEM = (4096 + 4096 + 3 * 32 * 65) * 4;   // 57728 B
    static const int NT_SMEM    = (1024 + 4096 + 3 * 64 * 65) * 4;   // 70400 B
    cudaFuncSetAttribute(embed_key_vk_kernel,    cudaFuncAttributeMaxDynamicSharedMemorySize, EMBED_SMEM);
    cudaFuncSetAttribute(newtotal_vk_all_kernel, cudaFuncAttributeMaxDynamicSharedMemorySize, NT_SMEM);

    // output offsets (floats)
    float* O_uE0   = out + 0;
    float* O_iE0   = out + 6400000;
    float* O_ulat  = out + 9600000;
    float* O_ilat  = out + 16000000;
    float* O_uKey  = out + 19200000;
    float* O_iKey  = out + 25600000;
    float* O_uHyp  = out + 28800000;
    float* O_iHyp  = out + 28808192;
    float* O_uuE0  = out + 28816384;
    float* O_uulat = out + 35216384;
    float* O_uuKey = out + 41616384;
    float* O_uuHyp = out + 48016384;

    route_kernel<<<1, 1>>>(d_in[8], d_in[9], d_in[10], d_in[11], d_in[12],
                           d_in[13], d_in[14], d_in[15], d_in[16]);
    cudaMemsetAsync(cntp, 0, (size_t)NROWS_TOT * sizeof(unsigned), 0);
    cudaMemsetAsync(scrp, 0, (size_t)3 * 4096 * sizeof(float), 0);

    // CSR build
    const int eGrid = (3 * NNZE + 255) / 256;
    hist3_kernel<<<eGrid, 256>>>();
    scan3_kernel<<<3, 1024>>>();
    scatter3_kernel<<<eGrid, 256>>>();

    // gather SpMM, 2 hops
    const int gGrid = NROWS_TOT / 16;   // 15625
    gather3_kernel<<<gGrid, 256>>>(iE, uE, uE, sp + Z_TU1, sp + Z_TI1, sp + Z_UU1);
    gather3_kernel<<<gGrid, 256>>>(sp + Z_TI1, sp + Z_TU1, sp + Z_UU1,
                                   sp + Z_TU2, sp + Z_TI2, sp + Z_UU2);

    copy_hyper_kernel<<<32, 256>>>(Hyp, O_uHyp, O_iHyp, O_uuHyp);

    // fused embed + key + layer-0 vp/Gram
    embed_key_vk_kernel<<<1480, 256, EMBED_SMEM>>>(uE, sp + Z_TU1, sp + Z_TU2, Ks + 0,
                                                   pVm + 0,    O_uE0,  O_uKey,  scrp + 0 * 4096, UN);
    embed_key_vk_kernel<<<1480, 256, EMBED_SMEM>>>(iE, sp + Z_TI1, sp + Z_TI2, Ks + 4096,
                                                   pVm + 4096, O_iE0,  O_iKey,  scrp + 1 * 4096, INUM);
    embed_key_vk_kernel<<<1480, 256, EMBED_SMEM>>>(uE, sp + Z_UU1, sp + Z_UU2, Ks + 8192,
                                                   pVm + 8192, O_uuE0, O_uuKey, scrp + 2 * 4096, UN);

    dim3 smallGrid(16, 3);
    dim3 rowGrid((UN + 63) / 64, 3);

    // layer 0
    t1t2_all_kernel<<<smallGrid, 256>>>(Hyp, W1, 0);
    t3pre_all_kernel<<<smallGrid, 256>>>(W2, Vm, Hyp, 0);
    newtotal_vk_all_kernel<<<rowGrid, 256, NT_SMEM>>>(O_uKey, O_iKey, O_uuKey,
                                                      O_uE0, O_iE0, O_uuE0,
                                                      O_ulat, O_ilat, O_uulat, pVm);
    // layer 1
    t1t2_all_kernel<<<smallGrid, 256>>>(Hyp, W1, 1);
    t3pre_all_kernel<<<smallGrid, 256>>>(W2, Vm, Hyp, 1);
    newtotal_final_all_kernel<<<rowGrid, 256>>>(O_uKey, O_iKey, O_uuKey,
                                                O_ulat, O_ilat, O_uulat);
}